// round 7
// baseline (speedup 1.0000x reference)
#include <cuda_runtime.h>
#include <cuda_bf16.h>
#include <cuda_fp16.h>
#include <cstdint>

#define BATCH 256
#define INF   1024
#define OUTF  128
#define KD    8
#define NCOLS (OUTF * KD)     // 1024
#define OUTW  (INF + OUTF)    // 1152

// Device scratch (no allocs allowed)
__device__ __align__(16) __half g_Mh[BATCH * NCOLS];   // M = x @ T, fp16
__device__ __nv_bfloat16 g_Abf[BATCH * INF];           // x in bf16 (K-major)
__device__ __nv_bfloat16 g_Bt[NCOLS * INF];            // T transposed: Bt[n][k]

__device__ __forceinline__ uint32_t smem_u32(const void* p) {
    uint32_t a;
    asm("{ .reg .u64 t; cvta.to.shared.u64 t, %1; cvt.u32.u64 %0, t; }" : "=r"(a) : "l"(p));
    return a;
}
#define SWZ128(b) ((b) ^ (((b) >> 3) & 0x70))
#define CP_ASYNC16(saddr, gptr) \
    asm volatile("cp.async.cg.shared.global [%0], [%1], 16;" :: "r"(saddr), "l"(gptr) : "memory")
#define CP_COMMIT() asm volatile("cp.async.commit_group;" ::: "memory")
#define CP_WAIT1()  asm volatile("cp.async.wait_group 1;" ::: "memory")

// ---------------------------------------------------------------------------
// Fused prep: blocks [0,1024) transpose+convert T; blocks [1024,1280) copy x
// into out[:, :1024] and convert x -> bf16.
// ---------------------------------------------------------------------------
__global__ __launch_bounds__(256) void prep_kernel(
    const float* __restrict__ x, const float* __restrict__ T,
    float* __restrict__ out, __nv_bfloat16* __restrict__ xb,
    __nv_bfloat16* __restrict__ Bt)
{
    if (blockIdx.x < 1024) {
        // Transpose a 32x32 tile of T.
        __shared__ float tile[32][33];
        const int bx = blockIdx.x & 31;      // n-tile
        const int by = blockIdx.x >> 5;      // k-tile
        const int tx = threadIdx.x & 31;
        const int ty = threadIdx.x >> 5;     // 0..7
        const int n = bx * 32 + tx;
        #pragma unroll
        for (int r = 0; r < 4; r++) {
            const int k = by * 32 + ty + r * 8;
            tile[ty + r * 8][tx] = T[k * NCOLS + n];
        }
        __syncthreads();
        const int k_out = by * 32 + tx;
        #pragma unroll
        for (int r = 0; r < 4; r++) {
            const int n_out = bx * 32 + ty + r * 8;
            Bt[n_out * INF + k_out] = __float2bfloat16(tile[tx][ty + r * 8]);
        }
    } else {
        const int idx = (blockIdx.x - 1024) * 256 + threadIdx.x;  // float4 index
        const float4 v = reinterpret_cast<const float4*>(x)[idx];
        const int row = idx >> 8;
        const int c4  = idx & 255;
        *reinterpret_cast<float4*>(&out[row * OUTW + c4 * 4]) = v;
        reinterpret_cast<__nv_bfloat162*>(xb)[idx * 2]     = __floats2bfloat162_rn(v.x, v.y);
        reinterpret_cast<__nv_bfloat162*>(xb)[idx * 2 + 1] = __floats2bfloat162_rn(v.z, v.w);
    }
}

// ---------------------------------------------------------------------------
// HMMA GEMM, 3-stage cp.async pipeline; epilogue writes fp16 M.
// CTA tile M=32 x N=64, BK=64 (16 chunks). 8 warps = 2(m) x 4(n);
// warp tile 16x16. Grid (16 nt, 8 mt) = 128 CTAs. smem 36KB.
// ---------------------------------------------------------------------------
#define STAGE_BYTES 12288
#define GEMM_SMEM   (3 * STAGE_BYTES)

__global__ __launch_bounds__(256) void gemm_mma_kernel(
    const __nv_bfloat16* __restrict__ A, const __nv_bfloat16* __restrict__ B,
    __half* __restrict__ C)
{
    extern __shared__ __align__(1024) char dsm[];

    const int tid = threadIdx.x;
    const int wid = tid >> 5;
    const int lid = tid & 31;
    const int nt = blockIdx.x;   // 0..15
    const int mt = blockIdx.y;   // 0..7
    const int w_m = wid >> 2;    // 0..1
    const int w_n = wid & 3;     // 0..3

    const uint32_t sbase = smem_u32(dsm);

    const __nv_bfloat16* Ag = A + (size_t)(mt * 32) * INF;
    const __nv_bfloat16* Bg = B + (size_t)(nt * 64) * INF;

    const int ld_row  = tid >> 3;
    const int ld_kc   = tid & 7;
    const uint32_t soff0 = SWZ128((uint32_t)(ld_row * 128 + ld_kc * 16));
    const uint32_t soff1 = SWZ128((uint32_t)((ld_row + 32) * 128 + ld_kc * 16));

    float c[2][4];
    #pragma unroll
    for (int j = 0; j < 2; j++)
        #pragma unroll
        for (int q = 0; q < 4; q++) c[j][q] = 0.0f;

    const int l7  = lid & 7;
    const int lb3 = (lid >> 3) & 1;
    const int lb4 = (lid >> 4) & 1;
    const int a_row_lane = l7 + lb3 * 8;
    const int b_row_lane = l7 + lb4 * 8;
    const int nb = w_n * 16;
    const int mb = w_m * 16;

    auto load_stage = [&](int st, int k0) {
        const uint32_t sA = sbase + st * STAGE_BYTES;
        const uint32_t sB = sA + 4096;
        const __nv_bfloat16* ga = Ag + ld_row * INF + k0 + ld_kc * 8;
        const __nv_bfloat16* gb = Bg + ld_row * INF + k0 + ld_kc * 8;
        CP_ASYNC16(sA + soff0, ga);
        CP_ASYNC16(sB + soff0, gb);
        CP_ASYNC16(sB + soff1, gb + 32 * INF);
    };

    load_stage(0, 0);   CP_COMMIT();
    load_stage(1, 64);  CP_COMMIT();

    for (int ch = 0; ch < 16; ch++) {
        CP_WAIT1();
        __syncthreads();
        if (ch + 2 < 16) load_stage((ch + 2) % 3, (ch + 2) * 64);
        CP_COMMIT();

        const uint32_t sA = sbase + (ch % 3) * STAGE_BYTES;
        const uint32_t sB = sA + 4096;

        #pragma unroll
        for (int s = 0; s < 4; s++) {
            uint32_t b0, b1, b2, b3;
            {
                const uint32_t boff = SWZ128(
                    (uint32_t)((nb + b_row_lane) * 128 + (s * 2 + lb3) * 16));
                asm volatile(
                    "ldmatrix.sync.aligned.m8n8.x4.shared.b16 {%0,%1,%2,%3}, [%4];"
                    : "=r"(b0), "=r"(b1), "=r"(b2), "=r"(b3) : "r"(sB + boff));
            }
            uint32_t a0, a1, a2, a3;
            {
                const uint32_t aoff = SWZ128(
                    (uint32_t)((mb + a_row_lane) * 128 + (s * 2 + lb4) * 16));
                asm volatile(
                    "ldmatrix.sync.aligned.m8n8.x4.shared.b16 {%0,%1,%2,%3}, [%4];"
                    : "=r"(a0), "=r"(a1), "=r"(a2), "=r"(a3) : "r"(sA + aoff));
            }
            asm volatile(
                "mma.sync.aligned.m16n8k16.row.col.f32.bf16.bf16.f32 "
                "{%0,%1,%2,%3}, {%4,%5,%6,%7}, {%8,%9}, {%0,%1,%2,%3};"
                : "+f"(c[0][0]), "+f"(c[0][1]), "+f"(c[0][2]), "+f"(c[0][3])
                : "r"(a0), "r"(a1), "r"(a2), "r"(a3), "r"(b0), "r"(b1));
            asm volatile(
                "mma.sync.aligned.m16n8k16.row.col.f32.bf16.bf16.f32 "
                "{%0,%1,%2,%3}, {%4,%5,%6,%7}, {%8,%9}, {%0,%1,%2,%3};"
                : "+f"(c[1][0]), "+f"(c[1][1]), "+f"(c[1][2]), "+f"(c[1][3])
                : "r"(a0), "r"(a1), "r"(a2), "r"(a3), "r"(b2), "r"(b3));
        }
    }

    const int g = lid >> 2;
    const int tig = lid & 3;
    const int row = mt * 32 + mb + g;
    #pragma unroll
    for (int nf = 0; nf < 2; nf++) {
        const int col = nt * 64 + nb + nf * 8 + tig * 2;
        *reinterpret_cast<__half2*>(&C[row * NCOLS + col]) =
            __floats2half2_rn(c[nf][0], c[nf][1]);
        *reinterpret_cast<__half2*>(&C[(row + 8) * NCOLS + col]) =
            __floats2half2_rn(c[nf][2], c[nf][3]);
    }
}

// ---------------------------------------------------------------------------
// Pairwise L1 + exp-sum, pure fp16x2 (no fp32 in the inner loop).
// Grid 512 = (o, i-quarter). 512 threads = 64 i-local x 8-way j-split (32 j).
// d lanes: t.low = sum over even k, t.high = odd k; d = t + swap(t) puts the
// full distance in BOTH lanes; h2exp2(-d*log2e) gives exp(-d) in both lanes.
// ---------------------------------------------------------------------------
__global__ __launch_bounds__(512) void pairwise_kernel(
    const __half* __restrict__ Mh, float* __restrict__ out)
{
    const int o  = blockIdx.x >> 2;       // 0..127
    const int iq = blockIdx.x & 3;        // 0..3
    const int il = threadIdx.x & 63;      // 0..63
    const int h  = threadIdx.x >> 6;      // 0..7
    const int i  = iq * 64 + il;

    __shared__ uint4 Ms[BATCH];
    __shared__ float psum[7][64];

    if (threadIdx.x < BATCH)
        Ms[threadIdx.x] = *reinterpret_cast<const uint4*>(
            &Mh[threadIdx.x * NCOLS + o * KD]);
    __syncthreads();

    uint4 av = Ms[i];
    const __half2 a0 = *reinterpret_cast<__half2*>(&av.x);
    const __half2 a1 = *reinterpret_cast<__half2*>(&av.y);
    const __half2 a2 = *reinterpret_cast<__half2*>(&av.z);
    const __half2 a3 = *reinterpret_cast<__half2*>(&av.w);

    const __half2 nlog2e = __float2half2_rn(-1.44269504089f);
    __half2 acc = __float2half2_rn(0.0f);

    const int j0 = h * 32;
    #pragma unroll 8
    for (int j = j0; j < j0 + 32; j++) {
        uint4 bv = Ms[j];   // warp-uniform j -> LDS broadcast
        const __half2 s0 = __hsub2(a0, *reinterpret_cast<__half2*>(&bv.x));
        const __half2 s1 = __hsub2(a1, *reinterpret_cast<__half2*>(&bv.y));
        const __half2 s2 = __hsub2(a2, *reinterpret_cast<__half2*>(&bv.z));
        const __half2 s3 = __hsub2(a3, *reinterpret_cast<__half2*>(&bv.w));
        const __half2 t = __hadd2(__hadd2(__habs2(s0), __habs2(s1)),
                                  __hadd2(__habs2(s2), __habs2(s3)));
        const __half2 d = __hadd2(t, __lowhigh2highlow(t));   // full dist, both lanes
        acc = __hadd2(acc, h2exp2(__hmul2(d, nlog2e)));
    }

    const float s = __low2float(acc);     // both lanes identical

    if (h) psum[h - 1][il] = s;
    __syncthreads();
    if (h == 0) {
        float tot = s - 1.0f;
        #pragma unroll
        for (int q = 0; q < 7; q++) tot += psum[q][il];
        out[i * OUTW + INF + o] = tot;
    }
}

// ---------------------------------------------------------------------------
extern "C" void kernel_launch(void* const* d_in, const int* in_sizes, int n_in,
                              void* d_out, int out_size)
{
    const float* x = (const float*)d_in[0];   // (256, 1024)
    const float* T = (const float*)d_in[1];   // (1024, 1024)
    float* out = (float*)d_out;               // (256, 1152)

    __half* Mh;
    __nv_bfloat16 *Abf, *Bt;
    cudaGetSymbolAddress((void**)&Mh, g_Mh);
    cudaGetSymbolAddress((void**)&Abf, g_Abf);
    cudaGetSymbolAddress((void**)&Bt, g_Bt);

    static bool attr_set = false;
    if (!attr_set) {
        cudaFuncSetAttribute(gemm_mma_kernel,
                             cudaFuncAttributeMaxDynamicSharedMemorySize, GEMM_SMEM);
        attr_set = true;
    }

    prep_kernel<<<1024 + 256, 256>>>(x, T, out, Abf, Bt);

    gemm_mma_kernel<<<dim3(NCOLS / 64, BATCH / 32), 256, GEMM_SMEM>>>(Abf, Bt, Mh);

    pairwise_kernel<<<4 * OUTF, 512>>>(Mh, out);
}

// round 8
// speedup vs baseline: 1.0015x; 1.0015x over previous
#include <cuda_runtime.h>
#include <cuda_bf16.h>
#include <cuda_fp16.h>
#include <cstdint>

#define BATCH 256
#define INF   1024
#define OUTF  128
#define KD    8
#define NCOLS (OUTF * KD)     // 1024
#define OUTW  (INF + OUTF)    // 1152

// Device scratch (no allocs allowed)
__device__ __align__(16) __half g_Mh[BATCH * NCOLS];   // M = x @ T, fp16
__device__ __nv_bfloat16 g_Abf[BATCH * INF];           // x in bf16 (K-major)
__device__ __nv_bfloat16 g_Tbf[INF * NCOLS];           // T in bf16, SAME [k][n] layout

__device__ __forceinline__ uint32_t smem_u32(const void* p) {
    uint32_t a;
    asm("{ .reg .u64 t; cvta.to.shared.u64 t, %1; cvt.u32.u64 %0, t; }" : "=r"(a) : "l"(p));
    return a;
}
#define SWZ128(b) ((b) ^ (((b) >> 3) & 0x70))
#define CP_ASYNC16(saddr, gptr) \
    asm volatile("cp.async.cg.shared.global [%0], [%1], 16;" :: "r"(saddr), "l"(gptr) : "memory")
#define CP_COMMIT() asm volatile("cp.async.commit_group;" ::: "memory")
#define CP_WAIT1()  asm volatile("cp.async.wait_group 1;" ::: "memory")

// ---------------------------------------------------------------------------
// Streaming prep (no transpose):
//   blocks [0,1024):    T fp32 -> bf16, layout unchanged [k][n]
//   blocks [1024,1280): copy x into out[:, :1024] + convert x -> bf16
// ---------------------------------------------------------------------------
__global__ __launch_bounds__(256) void prep_kernel(
    const float* __restrict__ x, const float* __restrict__ T,
    float* __restrict__ out, __nv_bfloat16* __restrict__ xb,
    __nv_bfloat16* __restrict__ Tb)
{
    if (blockIdx.x < 1024) {
        const int idx = blockIdx.x * 256 + threadIdx.x;   // float4 index in T
        const float4 v = reinterpret_cast<const float4*>(T)[idx];
        reinterpret_cast<__nv_bfloat162*>(Tb)[idx * 2]     = __floats2bfloat162_rn(v.x, v.y);
        reinterpret_cast<__nv_bfloat162*>(Tb)[idx * 2 + 1] = __floats2bfloat162_rn(v.z, v.w);
    } else {
        const int idx = (blockIdx.x - 1024) * 256 + threadIdx.x;  // float4 index in x
        const float4 v = reinterpret_cast<const float4*>(x)[idx];
        const int row = idx >> 8;
        const int c4  = idx & 255;
        *reinterpret_cast<float4*>(&out[row * OUTW + c4 * 4]) = v;
        reinterpret_cast<__nv_bfloat162*>(xb)[idx * 2]     = __floats2bfloat162_rn(v.x, v.y);
        reinterpret_cast<__nv_bfloat162*>(xb)[idx * 2 + 1] = __floats2bfloat162_rn(v.z, v.w);
    }
}

// ---------------------------------------------------------------------------
// HMMA GEMM, 3-stage cp.async pipeline; B consumed directly from [k][n]
// tiles of Tbf via ldmatrix.trans (no transpose prep needed).
// CTA tile M=32 x N=64, BK=64 (16 chunks). 8 warps = 2(m) x 4(n);
// warp tile 16x16. Grid (16 nt, 8 mt) = 128 CTAs.
// smem/stage: A 32rows x 128B = 4KB (K-major), B 64 k-rows x 128B = 8KB ([k][n]).
// ---------------------------------------------------------------------------
#define STAGE_BYTES 12288
#define GEMM_SMEM   (3 * STAGE_BYTES)

__global__ __launch_bounds__(256) void gemm_mma_kernel(
    const __nv_bfloat16* __restrict__ A, const __nv_bfloat16* __restrict__ Tb,
    __half* __restrict__ C)
{
    extern __shared__ __align__(1024) char dsm[];

    const int tid = threadIdx.x;
    const int wid = tid >> 5;
    const int lid = tid & 31;
    const int nt = blockIdx.x;   // 0..15
    const int mt = blockIdx.y;   // 0..7
    const int w_m = wid >> 2;    // 0..1
    const int w_n = wid & 3;     // 0..3

    const uint32_t sbase = smem_u32(dsm);

    const __nv_bfloat16* Ag = A + (size_t)(mt * 32) * INF;
    const __nv_bfloat16* Bg = Tb + nt * 64;          // [k][n] slice, row stride NCOLS

    const int ld_row  = tid >> 3;          // 0..31
    const int ld_kc   = tid & 7;           // 16B unit within 128B row
    const uint32_t soff0 = SWZ128((uint32_t)(ld_row * 128 + ld_kc * 16));
    const uint32_t soff1 = SWZ128((uint32_t)((ld_row + 32) * 128 + ld_kc * 16));

    float c[2][4];
    #pragma unroll
    for (int j = 0; j < 2; j++)
        #pragma unroll
        for (int q = 0; q < 4; q++) c[j][q] = 0.0f;

    const int l7  = lid & 7;
    const int lb3 = (lid >> 3) & 1;
    const int lb4 = (lid >> 4) & 1;
    const int a_row_lane = l7 + lb3 * 8;   // A: m-row within warp tile
    const int b_row_lane = l7 + lb3 * 8;   // B: k-row within 16-k step
    const int nb = w_n * 16;
    const int mb = w_m * 16;
    const uint32_t b_col_bytes = (uint32_t)(nb + 8 * lb4) * 2;  // n-block byte offset

    auto load_stage = [&](int st, int k0) {
        const uint32_t sA = sbase + st * STAGE_BYTES;
        const uint32_t sB = sA + 4096;
        const __nv_bfloat16* ga = Ag + ld_row * INF + k0 + ld_kc * 8;
        const __nv_bfloat16* gb = Bg + (size_t)(k0 + ld_row) * NCOLS + ld_kc * 8;
        CP_ASYNC16(sA + soff0, ga);                       // A: 32 rows
        CP_ASYNC16(sB + soff0, gb);                       // B: k rows 0..31
        CP_ASYNC16(sB + soff1, gb + 32 * NCOLS);          // B: k rows 32..63
    };

    load_stage(0, 0);   CP_COMMIT();
    load_stage(1, 64);  CP_COMMIT();

    for (int ch = 0; ch < 16; ch++) {
        CP_WAIT1();
        __syncthreads();
        if (ch + 2 < 16) load_stage((ch + 2) % 3, (ch + 2) * 64);
        CP_COMMIT();

        const uint32_t sA = sbase + (ch % 3) * STAGE_BYTES;
        const uint32_t sB = sA + 4096;

        #pragma unroll
        for (int s = 0; s < 4; s++) {
            // B fragments via transposing ldmatrix on the [k][n] tile:
            // lanes 0-7: k0-7/nblk0, 8-15: k8-15/nblk0, 16-23: k0-7/nblk1, 24-31: k8-15/nblk1
            uint32_t b0, b1, b2, b3;
            {
                const uint32_t boff = SWZ128(
                    (uint32_t)((s * 16 + b_row_lane) * 128) + b_col_bytes);
                asm volatile(
                    "ldmatrix.sync.aligned.m8n8.x4.trans.shared.b16 {%0,%1,%2,%3}, [%4];"
                    : "=r"(b0), "=r"(b1), "=r"(b2), "=r"(b3) : "r"(sB + boff));
            }
            uint32_t a0, a1, a2, a3;
            {
                const uint32_t aoff = SWZ128(
                    (uint32_t)((mb + a_row_lane) * 128 + (s * 2 + lb4) * 16));
                asm volatile(
                    "ldmatrix.sync.aligned.m8n8.x4.shared.b16 {%0,%1,%2,%3}, [%4];"
                    : "=r"(a0), "=r"(a1), "=r"(a2), "=r"(a3) : "r"(sA + aoff));
            }
            asm volatile(
                "mma.sync.aligned.m16n8k16.row.col.f32.bf16.bf16.f32 "
                "{%0,%1,%2,%3}, {%4,%5,%6,%7}, {%8,%9}, {%0,%1,%2,%3};"
                : "+f"(c[0][0]), "+f"(c[0][1]), "+f"(c[0][2]), "+f"(c[0][3])
                : "r"(a0), "r"(a1), "r"(a2), "r"(a3), "r"(b0), "r"(b1));
            asm volatile(
                "mma.sync.aligned.m16n8k16.row.col.f32.bf16.bf16.f32 "
                "{%0,%1,%2,%3}, {%4,%5,%6,%7}, {%8,%9}, {%0,%1,%2,%3};"
                : "+f"(c[1][0]), "+f"(c[1][1]), "+f"(c[1][2]), "+f"(c[1][3])
                : "r"(a0), "r"(a1), "r"(a2), "r"(a3), "r"(b2), "r"(b3));
        }
    }

    const int g = lid >> 2;
    const int tig = lid & 3;
    const int row = mt * 32 + mb + g;
    #pragma unroll
    for (int nf = 0; nf < 2; nf++) {
        const int col = nt * 64 + nb + nf * 8 + tig * 2;
        *reinterpret_cast<__half2*>(&C[row * NCOLS + col]) =
            __floats2half2_rn(c[nf][0], c[nf][1]);
        *reinterpret_cast<__half2*>(&C[(row + 8) * NCOLS + col]) =
            __floats2half2_rn(c[nf][2], c[nf][3]);
    }
}

// ---------------------------------------------------------------------------
// Pairwise L1 + exp-sum, pure fp16x2.
// Grid 512 = (o, i-quarter). 512 threads = 64 i-local x 8-way j-split (32 j).
// ---------------------------------------------------------------------------
__global__ __launch_bounds__(512) void pairwise_kernel(
    const __half* __restrict__ Mh, float* __restrict__ out)
{
    const int o  = blockIdx.x >> 2;       // 0..127
    const int iq = blockIdx.x & 3;        // 0..3
    const int il = threadIdx.x & 63;      // 0..63
    const int h  = threadIdx.x >> 6;      // 0..7
    const int i  = iq * 64 + il;

    __shared__ uint4 Ms[BATCH];
    __shared__ float psum[7][64];

    if (threadIdx.x < BATCH)
        Ms[threadIdx.x] = *reinterpret_cast<const uint4*>(
            &Mh[threadIdx.x * NCOLS + o * KD]);
    __syncthreads();

    uint4 av = Ms[i];
    const __half2 a0 = *reinterpret_cast<__half2*>(&av.x);
    const __half2 a1 = *reinterpret_cast<__half2*>(&av.y);
    const __half2 a2 = *reinterpret_cast<__half2*>(&av.z);
    const __half2 a3 = *reinterpret_cast<__half2*>(&av.w);

    const __half2 nlog2e = __float2half2_rn(-1.44269504089f);
    __half2 acc = __float2half2_rn(0.0f);

    const int j0 = h * 32;
    #pragma unroll 8
    for (int j = j0; j < j0 + 32; j++) {
        uint4 bv = Ms[j];   // warp-uniform j -> LDS broadcast
        const __half2 s0 = __hsub2(a0, *reinterpret_cast<__half2*>(&bv.x));
        const __half2 s1 = __hsub2(a1, *reinterpret_cast<__half2*>(&bv.y));
        const __half2 s2 = __hsub2(a2, *reinterpret_cast<__half2*>(&bv.z));
        const __half2 s3 = __hsub2(a3, *reinterpret_cast<__half2*>(&bv.w));
        const __half2 t = __hadd2(__hadd2(__habs2(s0), __habs2(s1)),
                                  __hadd2(__habs2(s2), __habs2(s3)));
        const __half2 d = __hadd2(t, __lowhigh2highlow(t));
        acc = __hadd2(acc, h2exp2(__hmul2(d, nlog2e)));
    }

    const float s = __low2float(acc);

    if (h) psum[h - 1][il] = s;
    __syncthreads();
    if (h == 0) {
        float tot = s - 1.0f;
        #pragma unroll
        for (int q = 0; q < 7; q++) tot += psum[q][il];
        out[i * OUTW + INF + o] = tot;
    }
}

// ---------------------------------------------------------------------------
extern "C" void kernel_launch(void* const* d_in, const int* in_sizes, int n_in,
                              void* d_out, int out_size)
{
    const float* x = (const float*)d_in[0];   // (256, 1024)
    const float* T = (const float*)d_in[1];   // (1024, 1024)
    float* out = (float*)d_out;               // (256, 1152)

    __half* Mh;
    __nv_bfloat16 *Abf, *Tbf;
    cudaGetSymbolAddress((void**)&Mh, g_Mh);
    cudaGetSymbolAddress((void**)&Abf, g_Abf);
    cudaGetSymbolAddress((void**)&Tbf, g_Tbf);

    static bool attr_set = false;
    if (!attr_set) {
        cudaFuncSetAttribute(gemm_mma_kernel,
                             cudaFuncAttributeMaxDynamicSharedMemorySize, GEMM_SMEM);
        attr_set = true;
    }

    prep_kernel<<<1024 + 256, 256>>>(x, T, out, Abf, Tbf);

    gemm_mma_kernel<<<dim3(NCOLS / 64, BATCH / 32), 256, GEMM_SMEM>>>(Abf, Tbf, Mh);

    pairwise_kernel<<<4 * OUTF, 512>>>(Mh, out);
}